// round 15
// baseline (speedup 1.0000x reference)
#include <cuda_runtime.h>

#define EMB 100
#define BOT 5
#define NT  256
#define B_  128
#define S_  2048
#define V_  50257
#define HW_ (((V_ + 3) / 4 + 3) & ~3)    // u32 words per row, 4 u8 counts each
#define FULLMASK 0xffffffffu

// Persistent globals: zero-initialized at load; every launch restores them to
// zero (hist: each CTA clears exactly the words it touched after both CTAs
// finished reading; flags: mutual set/spin/reset-peer; g_z/g_h: cleared by the
// output CTA after use). Deterministic: float adds of exactly two values into
// 0 are order-invariant (commutativity).
__device__ unsigned int g_hist[B_][HW_];
__device__ float        g_z[B_];
__device__ float        g_h[B_][BOT];
__device__ unsigned int g_f1[B_][2];    // "my REDGs are visible"
__device__ unsigned int g_f2[B_][2];    // "my count reads are done"
__device__ unsigned int g_f3[B_];       // "CTA0's h contribution is visible"

__device__ __forceinline__ unsigned int poll(unsigned int* p) {
    return atomicAdd(p, 0u);
}

// grid 2*B: CTAs {2b, 2b+1} each process half of row b (1024 tokens).
// 2 CTAs/SM co-resident, independent barrier domains.
__global__ void __launch_bounds__(NT, 2)
doc_model_kernel(const int* __restrict__ x,
                 const float* __restrict__ we,
                 const float* __restrict__ idf,
                 const float* __restrict__ fc1w,
                 const float* __restrict__ fc1b,
                 const float* __restrict__ fc2w,
                 const float* __restrict__ fc2b,
                 float* __restrict__ out,
                 int S, int V)
{
    __shared__ float stage[8 * 256];   // per-warp (offset,idf) pairs / dup queue
    __shared__ float zp[8];
    __shared__ float hw[8 * 6];        // fc1 warp partials
    __shared__ float hv[8];

    const int tid  = threadIdx.x;
    const int warp = tid >> 5;
    const int lane = tid & 31;
    const int b    = blockIdx.x >> 1;
    const int h    = blockIdx.x & 1;

    unsigned int* hrow = g_hist[b];

    // ---- this CTA's 1024 tokens: warp w owns [128w,128w+128) of the half,
    // lane l holds 4 tokens (one LDG.128).
    const int* xr = x + (long long)b * S + h * (S >> 1);
    const int4 t4 = *(const int4*)(xr + (warp << 7) + (lane << 2));
    const int w0 = t4.x >> 2, w1 = t4.y >> 2, w2 = t4.z >> 2, w3 = t4.w >> 2;

    // ---- L2 histogram increments (fire-and-forget; handshake f1 later)
    atomicAdd(&hrow[w0], 1u << ((t4.x & 3) << 3));
    atomicAdd(&hrow[w1], 1u << ((t4.y & 3) << 3));
    atomicAdd(&hrow[w2], 1u << ((t4.z & 3) << 3));
    atomicAdd(&hrow[w3], 1u << ((t4.w & 3) << 3));

    const float i0 = __ldg(&idf[t4.x]);
    const float i1 = __ldg(&idf[t4.y]);
    const float i2 = __ldg(&idf[t4.z]);
    const float i3 = __ldg(&idf[t4.w]);

    // ---- stage (byte-offset, idf) pairs (warp-private strips)
    float4* stW = (float4*)(stage + (warp << 8));
    stW[(lane << 1)]     = make_float4(__int_as_float(t4.x * (EMB * 4)), i0,
                                       __int_as_float(t4.y * (EMB * 4)), i1);
    stW[(lane << 1) + 1] = make_float4(__int_as_float(t4.z * (EMB * 4)), i2,
                                       __int_as_float(t4.w * (EMB * 4)), i3);

    float z = (i0 + i1) + (i2 + i3);
    #pragma unroll
    for (int o = 16; o; o >>= 1) z += __shfl_xor_sync(FULLMASK, z, o);
    if (lane == 0) zp[warp] = z;
    __syncthreads();                 // zp + all stage strips ready
    if (tid == 0) {
        float zo = 0.f;
        #pragma unroll
        for (int i = 0; i < 8; i++) zo += zp[i];
        atomicAdd(&g_z[b], zo);      // 2-way commutative: deterministic
    }

    // ---- MAIN GATHER (overlaps REDG completion; proven R7/R12 pipeline)
    const bool active = lane < (EMB / 4);
    const int  eoff   = lane << 4;
    const char* web = (const char*)we;
    float4 acc0 = make_float4(0.f, 0.f, 0.f, 0.f);
    float4 acc1 = make_float4(0.f, 0.f, 0.f, 0.f);

    #pragma unroll 2
    for (int kk = 0; kk < 64; kk += 4) {
        const float4 q0 = stW[kk];
        const float4 q1 = stW[kk + 1];
        const float4 q2 = stW[kk + 2];
        const float4 q3 = stW[kk + 3];
        if (active) {
            const float4 ea = *(const float4*)(web + __float_as_int(q0.x) + eoff);
            const float4 eb = *(const float4*)(web + __float_as_int(q0.z) + eoff);
            const float4 ec = *(const float4*)(web + __float_as_int(q1.x) + eoff);
            const float4 ed = *(const float4*)(web + __float_as_int(q1.z) + eoff);
            const float4 ee = *(const float4*)(web + __float_as_int(q2.x) + eoff);
            const float4 ef = *(const float4*)(web + __float_as_int(q2.z) + eoff);
            const float4 eg = *(const float4*)(web + __float_as_int(q3.x) + eoff);
            const float4 eh = *(const float4*)(web + __float_as_int(q3.z) + eoff);
            acc0.x += q0.y * ea.x; acc0.y += q0.y * ea.y; acc0.z += q0.y * ea.z; acc0.w += q0.y * ea.w;
            acc1.x += q0.w * eb.x; acc1.y += q0.w * eb.y; acc1.z += q0.w * eb.z; acc1.w += q0.w * eb.w;
            acc0.x += q1.y * ec.x; acc0.y += q1.y * ec.y; acc0.z += q1.y * ec.z; acc0.w += q1.y * ec.w;
            acc1.x += q1.w * ed.x; acc1.y += q1.w * ed.y; acc1.z += q1.w * ed.z; acc1.w += q1.w * ed.w;
            acc0.x += q2.y * ee.x; acc0.y += q2.y * ee.y; acc0.z += q2.y * ee.z; acc0.w += q2.y * ee.w;
            acc1.x += q2.w * ef.x; acc1.y += q2.w * ef.y; acc1.z += q2.w * ef.z; acc1.w += q2.w * ef.w;
            acc0.x += q3.y * eg.x; acc0.y += q3.y * eg.y; acc0.z += q3.y * eg.z; acc0.w += q3.y * eg.w;
            acc1.x += q3.w * eh.x; acc1.y += q3.w * eh.y; acc1.z += q3.w * eh.z; acc1.w += q3.w * eh.w;
        }
    }

    // ---- handshake f1: my REDGs (+ g_z add) globally visible <-> peer's too
    __threadfence();
    __syncthreads();
    if (tid == 0) {
        atomicExch(&g_f1[b][h], 1u);
        while (poll(&g_f1[b][h ^ 1]) == 0u) __nanosleep(64);
        atomicExch(&g_f1[b][h ^ 1], 0u);    // reset peer's flag (it never re-reads)
    }
    __syncthreads();
    __threadfence();

    // ---- full-row counts from L2; duplicate correction queue
    const unsigned n0 = (__ldcg(&hrow[w0]) >> ((t4.x & 3) << 3)) & 0xFFu;
    const unsigned n1 = (__ldcg(&hrow[w1]) >> ((t4.y & 3) << 3)) & 0xFFu;
    const unsigned n2 = (__ldcg(&hrow[w2]) >> ((t4.z & 3) << 3)) & 0xFFu;
    const unsigned n3 = (__ldcg(&hrow[w3]) >> ((t4.w & 3) << 3)) & 0xFFu;
    __syncwarp();                                   // strip reuse safe

    float2* q2 = (float2*)(stage + (warp << 8));    // capacity 128 entries
    int qlen = 0;
    {
        const unsigned lt = (1u << lane) - 1u;
        unsigned m;
        m = __ballot_sync(FULLMASK, n0 > 1);
        if (n0 > 1) q2[qlen + __popc(m & lt)] =
            make_float2(__int_as_float(t4.x * (EMB * 4)), (float)(n0 - 1) * i0);
        qlen += __popc(m);
        m = __ballot_sync(FULLMASK, n1 > 1);
        if (n1 > 1) q2[qlen + __popc(m & lt)] =
            make_float2(__int_as_float(t4.y * (EMB * 4)), (float)(n1 - 1) * i1);
        qlen += __popc(m);
        m = __ballot_sync(FULLMASK, n2 > 1);
        if (n2 > 1) q2[qlen + __popc(m & lt)] =
            make_float2(__int_as_float(t4.z * (EMB * 4)), (float)(n2 - 1) * i2);
        qlen += __popc(m);
        m = __ballot_sync(FULLMASK, n3 > 1);
        if (n3 > 1) q2[qlen + __popc(m & lt)] =
            make_float2(__int_as_float(t4.w * (EMB * 4)), (float)(n3 - 1) * i3);
        qlen += __popc(m);
    }
    __syncwarp();

    for (int j = 0; j < qlen; j++) {
        const float2 e = q2[j];
        if (active) {
            const float4 ev = *(const float4*)(web + __float_as_int(e.x) + eoff);
            acc0.x += e.y * ev.x; acc0.y += e.y * ev.y;
            acc0.z += e.y * ev.z; acc0.w += e.y * ev.w;
        }
    }

    // ---- fused fc1 warp partials (pre-invZ, pre-bias)
    acc0.x += acc1.x; acc0.y += acc1.y; acc0.z += acc1.z; acc0.w += acc1.w;
    #pragma unroll
    for (int j = 0; j < BOT; j++) {
        float s = 0.f;
        if (active) {
            const float4 w1v = *(const float4*)(fc1w + j * EMB + (lane << 2));
            s = acc0.x * w1v.x + acc0.y * w1v.y + acc0.z * w1v.z + acc0.w * w1v.w;
        }
        #pragma unroll
        for (int o = 16; o; o >>= 1) s += __shfl_xor_sync(FULLMASK, s, o);
        if (lane == 0) hw[warp * 6 + j] = s;
    }
    __syncthreads();   // hw ready; ALL count reads of this CTA are done

    // ---- handshake f2: both CTAs finished reading counts -> safe to clear
    if (tid == 0) {
        atomicExch(&g_f2[b][h], 1u);
        while (poll(&g_f2[b][h ^ 1]) == 0u) __nanosleep(64);
        atomicExch(&g_f2[b][h ^ 1], 0u);
    }
    __syncthreads();

    // clear exactly my touched words (overlapping zero-stores are benign)
    hrow[w0] = 0u; hrow[w1] = 0u; hrow[w2] = 0u; hrow[w3] = 0u;

    // ---- publish my 5 fc1 sums (2-way commutative float adds: deterministic)
    if (tid < BOT) {
        float hh = 0.f;
        #pragma unroll
        for (int w = 0; w < 8; w++) hh += hw[w * 6 + tid];
        atomicAdd(&g_h[b][tid], hh);
    }
    __threadfence();
    __syncthreads();

    if (h == 0) {
        if (tid == 0) atomicExch(&g_f3[b], 1u);   // CTA0: publish and exit
        return;
    }

    // CTA1: wait for CTA0's h, finish the MLP, write out, restore invariants
    if (tid == 0) {
        while (poll(&g_f3[b]) == 0u) __nanosleep(64);
        atomicExch(&g_f3[b], 0u);
    }
    __syncthreads();
    __threadfence();

    if (tid < BOT) {
        const float invZ = 1.0f / __ldcg(&g_z[b]);
        hv[tid] = __ldcg(&g_h[b][tid]) * invZ + __ldg(&fc1b[tid]);
    }
    __syncthreads();
    if (tid < EMB) {
        float o = __ldg(&fc2b[tid]);
        #pragma unroll
        for (int j = 0; j < BOT; j++) o += hv[j] * __ldg(&fc2w[tid * BOT + j]);
        out[(long long)b * EMB + tid] = o;
    }
    // restore scratch invariants for the next launch
    if (tid < BOT) g_h[b][tid] = 0.f;
    if (tid == 0)  g_z[b] = 0.f;
}

extern "C" void kernel_launch(void* const* d_in, const int* in_sizes, int n_in,
                              void* d_out, int out_size)
{
    const int*   x    = (const int*)  d_in[0];   // [B,S] int32 token ids
    const float* we   = (const float*)d_in[1];   // [V,EMB]
    const float* idf  = (const float*)d_in[2];   // [V]
    const float* fc1w = (const float*)d_in[3];   // [BOT,EMB]
    const float* fc1b = (const float*)d_in[4];   // [BOT]
    const float* fc2w = (const float*)d_in[5];   // [EMB,BOT]
    const float* fc2b = (const float*)d_in[6];   // [EMB]
    float* out = (float*)d_out;                  // [B,EMB]

    const int V = in_sizes[2];
    const int B = out_size / EMB;
    const int S = in_sizes[0] / B;

    doc_model_kernel<<<2 * B, NT>>>(x, we, idf, fc1w, fc1b, fc2w, fc2b,
                                    out, S, V);
}